// round 4
// baseline (speedup 1.0000x reference)
#include <cuda_runtime.h>

// 4-qubit depth-2 variational circuit, B=2^20 samples. Single fused kernel.
//
// z_w = psi^T A_w psi, A_w = Re(U^H Z_w U); psi real rank-1 product state.
// Per qubit v[b]v[b'] spans {1, cos(x pi), sin(x pi)}/2, so
//   z_w = sum_{k,l<9} T_w[k,l] * r01[k] * r23[l],
// r01 = outer((1,C0,S0),(1,C1,S1)), r23 = outer((1,C2,S2),(1,C3,S3)).
// T (81 float4) is batch-independent; computed per block into shared (cheap:
// ~1k cycles) to keep the whole thing one launch.
// Main loop: 4 samples/thread as two f32x2 packed pairs sharing each T load
// (8 packed FMA per LDS.128).

#define PACKX2(d, lo, hi) \
    asm("mov.b64 %0, {%1, %2};" : "=l"(d) : "f"(lo), "f"(hi))
#define UNPACKX2(lo, hi, s) \
    asm("mov.b64 {%0, %1}, %2;" : "=f"(lo), "=f"(hi) : "l"(s))
#define MULX2(d, a, b) \
    asm("mul.rn.f32x2 %0, %1, %2;" : "=l"(d) : "l"(a), "l"(b))
#define FMAX2(d, a, b, c) \
    asm("fma.rn.f32x2 %0, %1, %2, %3;" : "=l"(d) : "l"(a), "l"(b), "l"(c))

__global__ void __launch_bounds__(256) qc_fused_kernel(
    const float4* __restrict__ x, const float* __restrict__ w,
    float4* __restrict__ out, int q /* = B/4 */) {
    __shared__ float sUr[16][16], sUi[16][16];   // U[s][j]
    __shared__ float sA[4][16][16];              // A_w[j][jp]
    __shared__ float4 Ts[81];
    int tid = threadIdx.x;

    // ---- prep stage 1: 16 threads evolve basis columns (register-resident) ----
    if (tid < 16) {
        const int j = tid;
        float wv[16];
#pragma unroll
        for (int i = 0; i < 16; ++i) wv[i] = w[i];
        float re[16], im[16];
#pragma unroll
        for (int s = 0; s < 16; ++s) { re[s] = (s == j) ? 1.0f : 0.0f; im[s] = 0.0f; }
#pragma unroll
        for (int d = 0; d < 2; ++d) {
#pragma unroll
            for (int g = 0; g < 4; ++g) {
                const int cm = 8 >> g;
                const int tm = 8 >> ((g + 1) & 3);
                float tre[16], tim[16];
#pragma unroll
                for (int s = 0; s < 16; ++s) {
                    const int src = (s & cm) ? (s ^ tm) : s;
                    tre[s] = re[src]; tim[s] = im[src];
                }
#pragma unroll
                for (int s = 0; s < 16; ++s) { re[s] = tre[s]; im[s] = tim[s]; }
            }
#pragma unroll
            for (int qb = 0; qb < 4; ++qb) {
                const int m = 8 >> qb;
                float cy, sy; __sincosf(0.5f * wv[d * 8 + qb * 2 + 0], &sy, &cy);
#pragma unroll
                for (int s = 0; s < 16; ++s) {
                    if (s & m) continue;
                    const int s1 = s | m;
                    float r0 = re[s], i0 = im[s], r1 = re[s1], i1 = im[s1];
                    re[s]  = cy * r0 - sy * r1;  im[s]  = cy * i0 - sy * i1;
                    re[s1] = sy * r0 + cy * r1;  im[s1] = sy * i0 + cy * i1;
                }
                float cp, sp; __sincosf(0.5f * wv[d * 8 + qb * 2 + 1], &sp, &cp);
#pragma unroll
                for (int s = 0; s < 16; ++s) {
                    float r = re[s], i = im[s];
                    if (s & m) { re[s] = r * cp - i * sp;  im[s] = i * cp + r * sp; }
                    else       { re[s] = r * cp + i * sp;  im[s] = i * cp - r * sp; }
                }
            }
        }
#pragma unroll
        for (int s = 0; s < 16; ++s) { sUr[s][j] = re[s]; sUi[s][j] = im[s]; }
    }
    __syncthreads();

    // ---- prep stage 2: A_w[j][jp] ----
#pragma unroll
    for (int e = tid; e < 1024; e += 256) {
        int wq = e >> 8;
        int j  = (e >> 4) & 15;
        int jp = e & 15;
        int mask = 8 >> wq;
        float acc = 0.f;
#pragma unroll
        for (int s = 0; s < 16; ++s) {
            float v = sUr[s][j] * sUr[s][jp] + sUi[s][j] * sUi[s][jp];
            acc += (s & mask) ? -v : v;
        }
        sA[wq][j][jp] = acc;
    }
    __syncthreads();

    // ---- prep stage 3: sparse basis change A -> T (16 nonzero pairs each) ----
    if (tid < 81) {
        int k = tid / 9, l = tid % 9;
        int i0 = k / 3, i1 = k % 3, i2 = l / 3, i3 = l % 3;
        int x0 = (i0 == 2), x1 = (i1 == 2), x2 = (i2 == 2), x3 = (i3 == 2);
        int n0 = (i0 == 1), n1 = (i1 == 1), n2 = (i2 == 1), n3 = (i3 == 1);
        float t4[4] = {0.f, 0.f, 0.f, 0.f};
#pragma unroll
        for (int c = 0; c < 16; ++c) {
            int o0 = (c >> 3) & 1, o1 = (c >> 2) & 1, o2 = (c >> 1) & 1, o3 = c & 1;
            int j  = (o0 << 3) | (o1 << 2) | (o2 << 1) | o3;
            int jp = ((o0 ^ x0) << 3) | ((o1 ^ x1) << 2) | ((o2 ^ x2) << 1) | (o3 ^ x3);
            int neg = (n0 & o0) ^ (n1 & o1) ^ (n2 & o2) ^ (n3 & o3);
            float sgn = neg ? -1.0f : 1.0f;
#pragma unroll
            for (int wq = 0; wq < 4; ++wq) t4[wq] += sgn * sA[wq][j][jp];
        }
        const float inv16 = 1.0f / 16.0f;
        Ts[tid] = make_float4(t4[0] * inv16, t4[1] * inv16, t4[2] * inv16, t4[3] * inv16);
    }
    __syncthreads();

    // ---- main: 4 samples per thread (2 packed pairs) ----
    int t = blockIdx.x * 256 + tid;
    if (t >= q) return;

    const float PI_F = 3.14159265358979323846f;
    float4 xa = x[t];
    float4 xb = x[t + q];
    float4 xc = x[t + 2 * q];
    float4 xd = x[t + 3 * q];

    float Cq[4][4], Sq[4][4];  // [sample][qubit]
    __sincosf(xa.x * PI_F, &Sq[0][0], &Cq[0][0]);
    __sincosf(xa.y * PI_F, &Sq[0][1], &Cq[0][1]);
    __sincosf(xa.z * PI_F, &Sq[0][2], &Cq[0][2]);
    __sincosf(xa.w * PI_F, &Sq[0][3], &Cq[0][3]);
    __sincosf(xb.x * PI_F, &Sq[1][0], &Cq[1][0]);
    __sincosf(xb.y * PI_F, &Sq[1][1], &Cq[1][1]);
    __sincosf(xb.z * PI_F, &Sq[1][2], &Cq[1][2]);
    __sincosf(xb.w * PI_F, &Sq[1][3], &Cq[1][3]);
    __sincosf(xc.x * PI_F, &Sq[2][0], &Cq[2][0]);
    __sincosf(xc.y * PI_F, &Sq[2][1], &Cq[2][1]);
    __sincosf(xc.z * PI_F, &Sq[2][2], &Cq[2][2]);
    __sincosf(xc.w * PI_F, &Sq[2][3], &Cq[2][3]);
    __sincosf(xd.x * PI_F, &Sq[3][0], &Cq[3][0]);
    __sincosf(xd.y * PI_F, &Sq[3][1], &Cq[3][1]);
    __sincosf(xd.z * PI_F, &Sq[3][2], &Cq[3][2]);
    __sincosf(xd.w * PI_F, &Sq[3][3], &Cq[3][3]);

    // packed qubit factors: pair AB (samples 0,1), pair CD (samples 2,3)
    unsigned long long onep;
    PACKX2(onep, 1.0f, 1.0f);
    unsigned long long CAB[4], SAB[4], CCD[4], SCD[4];
#pragma unroll
    for (int qb = 0; qb < 4; ++qb) {
        PACKX2(CAB[qb], Cq[0][qb], Cq[1][qb]);
        PACKX2(SAB[qb], Sq[0][qb], Sq[1][qb]);
        PACKX2(CCD[qb], Cq[2][qb], Cq[3][qb]);
        PACKX2(SCD[qb], Sq[2][qb], Sq[3][qb]);
    }

    unsigned long long r01AB[9], r23AB[9], r01CD[9], r23CD[9];
    r01AB[0] = onep;    r01AB[1] = CAB[1];  r01AB[2] = SAB[1];
    r01AB[3] = CAB[0];  MULX2(r01AB[4], CAB[0], CAB[1]);  MULX2(r01AB[5], CAB[0], SAB[1]);
    r01AB[6] = SAB[0];  MULX2(r01AB[7], SAB[0], CAB[1]);  MULX2(r01AB[8], SAB[0], SAB[1]);
    r23AB[0] = onep;    r23AB[1] = CAB[3];  r23AB[2] = SAB[3];
    r23AB[3] = CAB[2];  MULX2(r23AB[4], CAB[2], CAB[3]);  MULX2(r23AB[5], CAB[2], SAB[3]);
    r23AB[6] = SAB[2];  MULX2(r23AB[7], SAB[2], CAB[3]);  MULX2(r23AB[8], SAB[2], SAB[3]);
    r01CD[0] = onep;    r01CD[1] = CCD[1];  r01CD[2] = SCD[1];
    r01CD[3] = CCD[0];  MULX2(r01CD[4], CCD[0], CCD[1]);  MULX2(r01CD[5], CCD[0], SCD[1]);
    r01CD[6] = SCD[0];  MULX2(r01CD[7], SCD[0], CCD[1]);  MULX2(r01CD[8], SCD[0], SCD[1]);
    r23CD[0] = onep;    r23CD[1] = CCD[3];  r23CD[2] = SCD[3];
    r23CD[3] = CCD[2];  MULX2(r23CD[4], CCD[2], CCD[3]);  MULX2(r23CD[5], CCD[2], SCD[3]);
    r23CD[6] = SCD[2];  MULX2(r23CD[7], SCD[2], CCD[3]);  MULX2(r23CD[8], SCD[2], SCD[3]);

    // z_w = sum_k r01[k] * (sum_l T_w[k,l] * r23[l]); both pairs share T loads
    unsigned long long aAB0 = 0ull, aAB1 = 0ull, aAB2 = 0ull, aAB3 = 0ull;
    unsigned long long aCD0 = 0ull, aCD1 = 0ull, aCD2 = 0ull, aCD3 = 0ull;
#pragma unroll
    for (int k = 0; k < 9; ++k) {
        unsigned long long sAB0 = 0ull, sAB1 = 0ull, sAB2 = 0ull, sAB3 = 0ull;
        unsigned long long sCD0 = 0ull, sCD1 = 0ull, sCD2 = 0ull, sCD3 = 0ull;
#pragma unroll
        for (int l = 0; l < 9; ++l) {
            float4 T = Ts[k * 9 + l];
            unsigned long long t0, t1, t2, t3;
            PACKX2(t0, T.x, T.x);
            PACKX2(t1, T.y, T.y);
            PACKX2(t2, T.z, T.z);
            PACKX2(t3, T.w, T.w);
            FMAX2(sAB0, t0, r23AB[l], sAB0);
            FMAX2(sAB1, t1, r23AB[l], sAB1);
            FMAX2(sAB2, t2, r23AB[l], sAB2);
            FMAX2(sAB3, t3, r23AB[l], sAB3);
            FMAX2(sCD0, t0, r23CD[l], sCD0);
            FMAX2(sCD1, t1, r23CD[l], sCD1);
            FMAX2(sCD2, t2, r23CD[l], sCD2);
            FMAX2(sCD3, t3, r23CD[l], sCD3);
        }
        FMAX2(aAB0, r01AB[k], sAB0, aAB0);
        FMAX2(aAB1, r01AB[k], sAB1, aAB1);
        FMAX2(aAB2, r01AB[k], sAB2, aAB2);
        FMAX2(aAB3, r01AB[k], sAB3, aAB3);
        FMAX2(aCD0, r01CD[k], sCD0, aCD0);
        FMAX2(aCD1, r01CD[k], sCD1, aCD1);
        FMAX2(aCD2, r01CD[k], sCD2, aCD2);
        FMAX2(aCD3, r01CD[k], sCD3, aCD3);
    }

    float zA0, zB0, zA1, zB1, zA2, zB2, zA3, zB3;
    float zC0, zD0, zC1, zD1, zC2, zD2, zC3, zD3;
    UNPACKX2(zA0, zB0, aAB0);  UNPACKX2(zA1, zB1, aAB1);
    UNPACKX2(zA2, zB2, aAB2);  UNPACKX2(zA3, zB3, aAB3);
    UNPACKX2(zC0, zD0, aCD0);  UNPACKX2(zC1, zD1, aCD1);
    UNPACKX2(zC2, zD2, aCD2);  UNPACKX2(zC3, zD3, aCD3);

    out[t]         = make_float4(zA0, zA1, zA2, zA3);
    out[t + q]     = make_float4(zB0, zB1, zB2, zB3);
    out[t + 2 * q] = make_float4(zC0, zC1, zC2, zC3);
    out[t + 3 * q] = make_float4(zD0, zD1, zD2, zD3);
}

extern "C" void kernel_launch(void* const* d_in, const int* in_sizes, int n_in,
                              void* d_out, int out_size) {
    const float* x = (const float*)d_in[0];       // [B,4]
    const float* w = (const float*)d_in[1];       // [2,4,2]
    float* out = (float*)d_out;                   // [B,4]
    int B = in_sizes[0] / 4;
    int q = B / 4;                                // samples per quarter

    int blocks = (q + 255) / 256;
    qc_fused_kernel<<<blocks, 256>>>((const float4*)x, w, (float4*)out, q);
}

// round 5
// speedup vs baseline: 1.0805x; 1.0805x over previous
#include <cuda_runtime.h>

// 4-qubit depth-2 variational circuit, B=2^20 samples.
// Two kernels: tiny prep (builds batch-independent 81x4 tensor T from weights)
// + main (4 samples/thread as two f32x2 pairs sharing every T load).
//
// z_w = sum_{k,l<9} T_w[k,l] * r01[k] * r23[l],
// r01 = outer((1,C0,S0),(1,C1,S1)), r23 = outer((1,C2,S2),(1,C3,S3)),
// Cq = cos(x_q*pi), Sq = sin(x_q*pi).

__device__ float4 g_T4[81];

#define PACKX2(d, lo, hi) \
    asm("mov.b64 %0, {%1, %2};" : "=l"(d) : "f"(lo), "f"(hi))
#define UNPACKX2(lo, hi, s) \
    asm("mov.b64 {%0, %1}, %2;" : "=f"(lo), "=f"(hi) : "l"(s))
#define MULX2(d, a, b) \
    asm("mul.rn.f32x2 %0, %1, %2;" : "=l"(d) : "l"(a), "l"(b))
#define FMAX2(d, a, b, c) \
    asm("fma.rn.f32x2 %0, %1, %2, %3;" : "=l"(d) : "l"(a), "l"(b), "l"(c))

// ---------------- prep ----------------
__global__ void __launch_bounds__(512) qc_prep_kernel(const float* __restrict__ w) {
    __shared__ float sUr[16][16], sUi[16][16];
    __shared__ float sA[4][16][16];
    int tid = threadIdx.x;

    if (tid < 16) {
        const int j = tid;
        float wv[16];
#pragma unroll
        for (int i = 0; i < 16; ++i) wv[i] = w[i];
        float re[16], im[16];
#pragma unroll
        for (int s = 0; s < 16; ++s) { re[s] = (s == j) ? 1.0f : 0.0f; im[s] = 0.0f; }
#pragma unroll
        for (int d = 0; d < 2; ++d) {
#pragma unroll
            for (int g = 0; g < 4; ++g) {
                const int cm = 8 >> g;
                const int tm = 8 >> ((g + 1) & 3);
                float tre[16], tim[16];
#pragma unroll
                for (int s = 0; s < 16; ++s) {
                    const int src = (s & cm) ? (s ^ tm) : s;
                    tre[s] = re[src]; tim[s] = im[src];
                }
#pragma unroll
                for (int s = 0; s < 16; ++s) { re[s] = tre[s]; im[s] = tim[s]; }
            }
#pragma unroll
            for (int qb = 0; qb < 4; ++qb) {
                const int m = 8 >> qb;
                float cy, sy; sincosf(0.5f * wv[d * 8 + qb * 2 + 0], &sy, &cy);
#pragma unroll
                for (int s = 0; s < 16; ++s) {
                    if (s & m) continue;
                    const int s1 = s | m;
                    float r0 = re[s], i0 = im[s], r1 = re[s1], i1 = im[s1];
                    re[s]  = cy * r0 - sy * r1;  im[s]  = cy * i0 - sy * i1;
                    re[s1] = sy * r0 + cy * r1;  im[s1] = sy * i0 + cy * i1;
                }
                float cp, sp; sincosf(0.5f * wv[d * 8 + qb * 2 + 1], &sp, &cp);
#pragma unroll
                for (int s = 0; s < 16; ++s) {
                    float r = re[s], i = im[s];
                    if (s & m) { re[s] = r * cp - i * sp;  im[s] = i * cp + r * sp; }
                    else       { re[s] = r * cp + i * sp;  im[s] = i * cp - r * sp; }
                }
            }
        }
#pragma unroll
        for (int s = 0; s < 16; ++s) { sUr[s][j] = re[s]; sUi[s][j] = im[s]; }
    }
    __syncthreads();

    for (int e = tid; e < 1024; e += 512) {
        int wq = e >> 8;
        int j  = (e >> 4) & 15;
        int jp = e & 15;
        int mask = 8 >> wq;
        float acc = 0.f;
#pragma unroll
        for (int s = 0; s < 16; ++s) {
            float v = sUr[s][j] * sUr[s][jp] + sUi[s][j] * sUi[s][jp];
            acc += (s & mask) ? -v : v;
        }
        sA[wq][j][jp] = acc;
    }
    __syncthreads();

    // sparse basis change: 16 nonzero (j,jp) pairs per (wire,k,l)
    if (tid < 324) {
        int wq = tid / 81;
        int kl = tid - wq * 81;
        int k = kl / 9, l = kl % 9;
        int i0 = k / 3, i1 = k % 3, i2 = l / 3, i3 = l % 3;
        int x0 = (i0 == 2), x1 = (i1 == 2), x2 = (i2 == 2), x3 = (i3 == 2);
        int n0 = (i0 == 1), n1 = (i1 == 1), n2 = (i2 == 1), n3 = (i3 == 1);
        float acc = 0.f;
#pragma unroll
        for (int c = 0; c < 16; ++c) {
            int o0 = (c >> 3) & 1, o1 = (c >> 2) & 1, o2 = (c >> 1) & 1, o3 = c & 1;
            int j  = (o0 << 3) | (o1 << 2) | (o2 << 1) | o3;
            int jp = ((o0 ^ x0) << 3) | ((o1 ^ x1) << 2) | ((o2 ^ x2) << 1) | (o3 ^ x3);
            int neg = (n0 & o0) ^ (n1 & o1) ^ (n2 & o2) ^ (n3 & o3);
            float v = sA[wq][j][jp];
            acc += neg ? -v : v;
        }
        ((float*)g_T4)[kl * 4 + wq] = acc * (1.0f / 16.0f);
    }
}

// ---------------- main: 4 samples/thread (2 packed pairs) ----------------
__global__ void __launch_bounds__(256) qc_main_kernel(
    const float4* __restrict__ x, float4* __restrict__ out, int q /* B/4 */) {
    __shared__ float4 Ts[81];
    int tid = threadIdx.x;
    if (tid < 81) Ts[tid] = g_T4[tid];
    __syncthreads();

    int t = blockIdx.x * 256 + tid;
    if (t >= q) return;

    const float PI_F = 3.14159265358979323846f;
    float4 xa = x[t];
    float4 xb = x[t + q];
    float4 xc = x[t + 2 * q];
    float4 xd = x[t + 3 * q];

    float Cq[4][4], Sq[4][4];  // [sample][qubit]
    __sincosf(xa.x * PI_F, &Sq[0][0], &Cq[0][0]);
    __sincosf(xa.y * PI_F, &Sq[0][1], &Cq[0][1]);
    __sincosf(xa.z * PI_F, &Sq[0][2], &Cq[0][2]);
    __sincosf(xa.w * PI_F, &Sq[0][3], &Cq[0][3]);
    __sincosf(xb.x * PI_F, &Sq[1][0], &Cq[1][0]);
    __sincosf(xb.y * PI_F, &Sq[1][1], &Cq[1][1]);
    __sincosf(xb.z * PI_F, &Sq[1][2], &Cq[1][2]);
    __sincosf(xb.w * PI_F, &Sq[1][3], &Cq[1][3]);
    __sincosf(xc.x * PI_F, &Sq[2][0], &Cq[2][0]);
    __sincosf(xc.y * PI_F, &Sq[2][1], &Cq[2][1]);
    __sincosf(xc.z * PI_F, &Sq[2][2], &Cq[2][2]);
    __sincosf(xc.w * PI_F, &Sq[2][3], &Cq[2][3]);
    __sincosf(xd.x * PI_F, &Sq[3][0], &Cq[3][0]);
    __sincosf(xd.y * PI_F, &Sq[3][1], &Cq[3][1]);
    __sincosf(xd.z * PI_F, &Sq[3][2], &Cq[3][2]);
    __sincosf(xd.w * PI_F, &Sq[3][3], &Cq[3][3]);

    unsigned long long onep;
    PACKX2(onep, 1.0f, 1.0f);
    unsigned long long CAB[4], SAB[4], CCD[4], SCD[4];
#pragma unroll
    for (int qb = 0; qb < 4; ++qb) {
        PACKX2(CAB[qb], Cq[0][qb], Cq[1][qb]);
        PACKX2(SAB[qb], Sq[0][qb], Sq[1][qb]);
        PACKX2(CCD[qb], Cq[2][qb], Cq[3][qb]);
        PACKX2(SCD[qb], Sq[2][qb], Sq[3][qb]);
    }

    unsigned long long r01AB[9], r23AB[9], r01CD[9], r23CD[9];
    r01AB[0] = onep;    r01AB[1] = CAB[1];  r01AB[2] = SAB[1];
    r01AB[3] = CAB[0];  MULX2(r01AB[4], CAB[0], CAB[1]);  MULX2(r01AB[5], CAB[0], SAB[1]);
    r01AB[6] = SAB[0];  MULX2(r01AB[7], SAB[0], CAB[1]);  MULX2(r01AB[8], SAB[0], SAB[1]);
    r23AB[0] = onep;    r23AB[1] = CAB[3];  r23AB[2] = SAB[3];
    r23AB[3] = CAB[2];  MULX2(r23AB[4], CAB[2], CAB[3]);  MULX2(r23AB[5], CAB[2], SAB[3]);
    r23AB[6] = SAB[2];  MULX2(r23AB[7], SAB[2], CAB[3]);  MULX2(r23AB[8], SAB[2], SAB[3]);
    r01CD[0] = onep;    r01CD[1] = CCD[1];  r01CD[2] = SCD[1];
    r01CD[3] = CCD[0];  MULX2(r01CD[4], CCD[0], CCD[1]);  MULX2(r01CD[5], CCD[0], SCD[1]);
    r01CD[6] = SCD[0];  MULX2(r01CD[7], SCD[0], CCD[1]);  MULX2(r01CD[8], SCD[0], SCD[1]);
    r23CD[0] = onep;    r23CD[1] = CCD[3];  r23CD[2] = SCD[3];
    r23CD[3] = CCD[2];  MULX2(r23CD[4], CCD[2], CCD[3]);  MULX2(r23CD[5], CCD[2], SCD[3]);
    r23CD[6] = SCD[2];  MULX2(r23CD[7], SCD[2], CCD[3]);  MULX2(r23CD[8], SCD[2], SCD[3]);

    // z_w = sum_k r01[k] * (sum_l T_w[k,l] * r23[l]); both pairs share T loads
    unsigned long long aAB0 = 0ull, aAB1 = 0ull, aAB2 = 0ull, aAB3 = 0ull;
    unsigned long long aCD0 = 0ull, aCD1 = 0ull, aCD2 = 0ull, aCD3 = 0ull;
#pragma unroll
    for (int k = 0; k < 9; ++k) {
        unsigned long long sAB0 = 0ull, sAB1 = 0ull, sAB2 = 0ull, sAB3 = 0ull;
        unsigned long long sCD0 = 0ull, sCD1 = 0ull, sCD2 = 0ull, sCD3 = 0ull;
#pragma unroll
        for (int l = 0; l < 9; ++l) {
            float4 T = Ts[k * 9 + l];
            unsigned long long t0, t1, t2, t3;
            PACKX2(t0, T.x, T.x);
            PACKX2(t1, T.y, T.y);
            PACKX2(t2, T.z, T.z);
            PACKX2(t3, T.w, T.w);
            FMAX2(sAB0, t0, r23AB[l], sAB0);
            FMAX2(sCD0, t0, r23CD[l], sCD0);
            FMAX2(sAB1, t1, r23AB[l], sAB1);
            FMAX2(sCD1, t1, r23CD[l], sCD1);
            FMAX2(sAB2, t2, r23AB[l], sAB2);
            FMAX2(sCD2, t2, r23CD[l], sCD2);
            FMAX2(sAB3, t3, r23AB[l], sAB3);
            FMAX2(sCD3, t3, r23CD[l], sCD3);
        }
        FMAX2(aAB0, r01AB[k], sAB0, aAB0);
        FMAX2(aCD0, r01CD[k], sCD0, aCD0);
        FMAX2(aAB1, r01AB[k], sAB1, aAB1);
        FMAX2(aCD1, r01CD[k], sCD1, aCD1);
        FMAX2(aAB2, r01AB[k], sAB2, aAB2);
        FMAX2(aCD2, r01CD[k], sCD2, aCD2);
        FMAX2(aAB3, r01AB[k], sAB3, aAB3);
        FMAX2(aCD3, r01CD[k], sCD3, aCD3);
    }

    float zA0, zB0, zA1, zB1, zA2, zB2, zA3, zB3;
    float zC0, zD0, zC1, zD1, zC2, zD2, zC3, zD3;
    UNPACKX2(zA0, zB0, aAB0);  UNPACKX2(zA1, zB1, aAB1);
    UNPACKX2(zA2, zB2, aAB2);  UNPACKX2(zA3, zB3, aAB3);
    UNPACKX2(zC0, zD0, aCD0);  UNPACKX2(zC1, zD1, aCD1);
    UNPACKX2(zC2, zD2, aCD2);  UNPACKX2(zC3, zD3, aCD3);

    out[t]         = make_float4(zA0, zA1, zA2, zA3);
    out[t + q]     = make_float4(zB0, zB1, zB2, zB3);
    out[t + 2 * q] = make_float4(zC0, zC1, zC2, zC3);
    out[t + 3 * q] = make_float4(zD0, zD1, zD2, zD3);
}

extern "C" void kernel_launch(void* const* d_in, const int* in_sizes, int n_in,
                              void* d_out, int out_size) {
    const float* x = (const float*)d_in[0];       // [B,4]
    const float* w = (const float*)d_in[1];       // [2,4,2]
    float* out = (float*)d_out;                   // [B,4]
    int B = in_sizes[0] / 4;
    int q = B / 4;

    qc_prep_kernel<<<1, 512>>>(w);
    int blocks = (q + 255) / 256;
    qc_main_kernel<<<blocks, 256>>>((const float4*)x, (float4*)out, q);
}

// round 6
// speedup vs baseline: 1.2573x; 1.1636x over previous
#include <cuda_runtime.h>

// 4-qubit depth-2 variational circuit, B=2^20 samples.
// prep kernel: builds batch-independent tensor T_w[i0,i1,i2,i3] (81 float4).
// main kernel: 4 samples/thread (two f32x2 pairs AB/CD sharing all T loads),
// fully-factored contraction
//   z_w = sum_{i0} r0[i0] sum_{i1} r1[i1] sum_{i2} r2[i2] sum_{i3} r3[i3] T
// with r_q = (1, cos(x_q pi), sin(x_q pi)) -> minimal live registers.

__device__ float4 g_T4[81];

#define PACKX2(d, lo, hi) \
    asm("mov.b64 %0, {%1, %2};" : "=l"(d) : "f"(lo), "f"(hi))
#define UNPACKX2(lo, hi, s) \
    asm("mov.b64 {%0, %1}, %2;" : "=f"(lo), "=f"(hi) : "l"(s))
#define FMAX2(d, a, b, c) \
    asm("fma.rn.f32x2 %0, %1, %2, %3;" : "=l"(d) : "l"(a), "l"(b), "l"(c))

// ---------------- prep ----------------
__global__ void __launch_bounds__(512) qc_prep_kernel(const float* __restrict__ w) {
    __shared__ float sUr[16][16], sUi[16][16];
    __shared__ float sA[4][16][16];
    int tid = threadIdx.x;

    if (tid < 16) {
        const int j = tid;
        float wv[16];
#pragma unroll
        for (int i = 0; i < 16; ++i) wv[i] = w[i];
        float re[16], im[16];
#pragma unroll
        for (int s = 0; s < 16; ++s) { re[s] = (s == j) ? 1.0f : 0.0f; im[s] = 0.0f; }
#pragma unroll
        for (int d = 0; d < 2; ++d) {
#pragma unroll
            for (int g = 0; g < 4; ++g) {
                const int cm = 8 >> g;
                const int tm = 8 >> ((g + 1) & 3);
                float tre[16], tim[16];
#pragma unroll
                for (int s = 0; s < 16; ++s) {
                    const int src = (s & cm) ? (s ^ tm) : s;
                    tre[s] = re[src]; tim[s] = im[src];
                }
#pragma unroll
                for (int s = 0; s < 16; ++s) { re[s] = tre[s]; im[s] = tim[s]; }
            }
#pragma unroll
            for (int qb = 0; qb < 4; ++qb) {
                const int m = 8 >> qb;
                float cy, sy; __sincosf(0.5f * wv[d * 8 + qb * 2 + 0], &sy, &cy);
#pragma unroll
                for (int s = 0; s < 16; ++s) {
                    if (s & m) continue;
                    const int s1 = s | m;
                    float r0 = re[s], i0 = im[s], r1 = re[s1], i1 = im[s1];
                    re[s]  = cy * r0 - sy * r1;  im[s]  = cy * i0 - sy * i1;
                    re[s1] = sy * r0 + cy * r1;  im[s1] = sy * i0 + cy * i1;
                }
                float cp, sp; __sincosf(0.5f * wv[d * 8 + qb * 2 + 1], &sp, &cp);
#pragma unroll
                for (int s = 0; s < 16; ++s) {
                    float r = re[s], i = im[s];
                    if (s & m) { re[s] = r * cp - i * sp;  im[s] = i * cp + r * sp; }
                    else       { re[s] = r * cp + i * sp;  im[s] = i * cp - r * sp; }
                }
            }
        }
#pragma unroll
        for (int s = 0; s < 16; ++s) { sUr[s][j] = re[s]; sUi[s][j] = im[s]; }
    }
    __syncthreads();

    for (int e = tid; e < 1024; e += 512) {
        int wq = e >> 8;
        int j  = (e >> 4) & 15;
        int jp = e & 15;
        int mask = 8 >> wq;
        float acc = 0.f;
#pragma unroll
        for (int s = 0; s < 16; ++s) {
            float v = sUr[s][j] * sUr[s][jp] + sUi[s][j] * sUi[s][jp];
            acc += (s & mask) ? -v : v;
        }
        sA[wq][j][jp] = acc;
    }
    __syncthreads();

    if (tid < 324) {
        int wq = tid / 81;
        int kl = tid - wq * 81;
        int k = kl / 9, l = kl % 9;
        int i0 = k / 3, i1 = k % 3, i2 = l / 3, i3 = l % 3;
        int x0 = (i0 == 2), x1 = (i1 == 2), x2 = (i2 == 2), x3 = (i3 == 2);
        int n0 = (i0 == 1), n1 = (i1 == 1), n2 = (i2 == 1), n3 = (i3 == 1);
        float acc = 0.f;
#pragma unroll
        for (int c = 0; c < 16; ++c) {
            int o0 = (c >> 3) & 1, o1 = (c >> 2) & 1, o2 = (c >> 1) & 1, o3 = c & 1;
            int j  = (o0 << 3) | (o1 << 2) | (o2 << 1) | o3;
            int jp = ((o0 ^ x0) << 3) | ((o1 ^ x1) << 2) | ((o2 ^ x2) << 1) | (o3 ^ x3);
            int neg = (n0 & o0) ^ (n1 & o1) ^ (n2 & o2) ^ (n3 & o3);
            float v = sA[wq][j][jp];
            acc += neg ? -v : v;
        }
        ((float*)g_T4)[kl * 4 + wq] = acc * (1.0f / 16.0f);
    }
}

// ---------------- main ----------------
__global__ void __launch_bounds__(128, 5) qc_main_kernel(
    const float4* __restrict__ x, float4* __restrict__ out, int q /* B/4 */) {
    __shared__ float4 Ts[81];
    int tid = threadIdx.x;
    if (tid < 81) Ts[tid] = g_T4[tid];
    __syncthreads();

    int t = blockIdx.x * 128 + tid;
    if (t >= q) return;

    const float PI_F = 3.14159265358979323846f;
    float4 xa = x[t];
    float4 xb = x[t + q];
    float4 xc = x[t + 2 * q];
    float4 xd = x[t + 3 * q];

    float Cs[4][4], Ss[4][4];  // [sample][qubit]
    __sincosf(xa.x * PI_F, &Ss[0][0], &Cs[0][0]);
    __sincosf(xa.y * PI_F, &Ss[0][1], &Cs[0][1]);
    __sincosf(xa.z * PI_F, &Ss[0][2], &Cs[0][2]);
    __sincosf(xa.w * PI_F, &Ss[0][3], &Cs[0][3]);
    __sincosf(xb.x * PI_F, &Ss[1][0], &Cs[1][0]);
    __sincosf(xb.y * PI_F, &Ss[1][1], &Cs[1][1]);
    __sincosf(xb.z * PI_F, &Ss[1][2], &Cs[1][2]);
    __sincosf(xb.w * PI_F, &Ss[1][3], &Cs[1][3]);
    __sincosf(xc.x * PI_F, &Ss[2][0], &Cs[2][0]);
    __sincosf(xc.y * PI_F, &Ss[2][1], &Cs[2][1]);
    __sincosf(xc.z * PI_F, &Ss[2][2], &Cs[2][2]);
    __sincosf(xc.w * PI_F, &Ss[2][3], &Cs[2][3]);
    __sincosf(xd.x * PI_F, &Ss[3][0], &Cs[3][0]);
    __sincosf(xd.y * PI_F, &Ss[3][1], &Cs[3][1]);
    __sincosf(xd.z * PI_F, &Ss[3][2], &Cs[3][2]);
    __sincosf(xd.w * PI_F, &Ss[3][3], &Cs[3][3]);

    // packed per-qubit factors for pair AB (samples 0,1) and CD (2,3)
    unsigned long long CAB[4], SAB[4], CCD[4], SCD[4];
#pragma unroll
    for (int qb = 0; qb < 4; ++qb) {
        PACKX2(CAB[qb], Cs[0][qb], Cs[1][qb]);
        PACKX2(SAB[qb], Ss[0][qb], Ss[1][qb]);
        PACKX2(CCD[qb], Cs[2][qb], Cs[3][qb]);
        PACKX2(SCD[qb], Ss[2][qb], Ss[3][qb]);
    }

    unsigned long long zAB[4], zCD[4];

// one wire component (w), both pairs: build v = Ta + C3*Tb + S3*Tc and fold
// into u with the r2 factor selected by compile-time i2.
#define ONEW(w, aa, bb, cc)                                            \
    {                                                                  \
        unsigned long long ta, tb, tc, vAB, vCD;                       \
        PACKX2(ta, aa, aa);                                            \
        PACKX2(tb, bb, bb);                                            \
        PACKX2(tc, cc, cc);                                            \
        FMAX2(vAB, CAB[3], tb, ta);                                    \
        FMAX2(vCD, CCD[3], tb, ta);                                    \
        FMAX2(vAB, SAB[3], tc, vAB);                                   \
        FMAX2(vCD, SCD[3], tc, vCD);                                   \
        if (i2 == 0) { uAB[w] = vAB; uCD[w] = vCD; }                   \
        else if (i2 == 1) {                                            \
            FMAX2(uAB[w], CAB[2], vAB, uAB[w]);                        \
            FMAX2(uCD[w], CCD[2], vCD, uCD[w]);                        \
        } else {                                                       \
            FMAX2(uAB[w], SAB[2], vAB, uAB[w]);                        \
            FMAX2(uCD[w], SCD[2], vCD, uCD[w]);                        \
        }                                                              \
    }

#pragma unroll
    for (int i0 = 0; i0 < 3; ++i0) {
        unsigned long long tAB[4], tCD[4];
#pragma unroll
        for (int i1 = 0; i1 < 3; ++i1) {
            const int base = (i0 * 3 + i1) * 9;
            unsigned long long uAB[4], uCD[4];
#pragma unroll
            for (int i2 = 0; i2 < 3; ++i2) {
                float4 Ta = Ts[base + i2 * 3 + 0];
                float4 Tb = Ts[base + i2 * 3 + 1];
                float4 Tc = Ts[base + i2 * 3 + 2];
                ONEW(0, Ta.x, Tb.x, Tc.x)
                ONEW(1, Ta.y, Tb.y, Tc.y)
                ONEW(2, Ta.z, Tb.z, Tc.z)
                ONEW(3, Ta.w, Tb.w, Tc.w)
            }
#pragma unroll
            for (int w = 0; w < 4; ++w) {
                if (i1 == 0) { tAB[w] = uAB[w]; tCD[w] = uCD[w]; }
                else if (i1 == 1) {
                    FMAX2(tAB[w], CAB[1], uAB[w], tAB[w]);
                    FMAX2(tCD[w], CCD[1], uCD[w], tCD[w]);
                } else {
                    FMAX2(tAB[w], SAB[1], uAB[w], tAB[w]);
                    FMAX2(tCD[w], SCD[1], uCD[w], tCD[w]);
                }
            }
        }
#pragma unroll
        for (int w = 0; w < 4; ++w) {
            if (i0 == 0) { zAB[w] = tAB[w]; zCD[w] = tCD[w]; }
            else if (i0 == 1) {
                FMAX2(zAB[w], CAB[0], tAB[w], zAB[w]);
                FMAX2(zCD[w], CCD[0], tCD[w], zCD[w]);
            } else {
                FMAX2(zAB[w], SAB[0], tAB[w], zAB[w]);
                FMAX2(zCD[w], SCD[0], tCD[w], zCD[w]);
            }
        }
    }
#undef ONEW

    float zA[4], zB[4], zC[4], zD[4];
#pragma unroll
    for (int w = 0; w < 4; ++w) {
        UNPACKX2(zA[w], zB[w], zAB[w]);
        UNPACKX2(zC[w], zD[w], zCD[w]);
    }

    out[t]         = make_float4(zA[0], zA[1], zA[2], zA[3]);
    out[t + q]     = make_float4(zB[0], zB[1], zB[2], zB[3]);
    out[t + 2 * q] = make_float4(zC[0], zC[1], zC[2], zC[3]);
    out[t + 3 * q] = make_float4(zD[0], zD[1], zD[2], zD[3]);
}

extern "C" void kernel_launch(void* const* d_in, const int* in_sizes, int n_in,
                              void* d_out, int out_size) {
    const float* x = (const float*)d_in[0];       // [B,4]
    const float* w = (const float*)d_in[1];       // [2,4,2]
    float* out = (float*)d_out;                   // [B,4]
    int B = in_sizes[0] / 4;
    int q = B / 4;

    qc_prep_kernel<<<1, 512>>>(w);
    int blocks = (q + 127) / 128;
    qc_main_kernel<<<blocks, 128>>>((const float4*)x, (float4*)out, q);
}

// round 7
// speedup vs baseline: 1.2752x; 1.0142x over previous
#include <cuda_runtime.h>

// 4-qubit depth-2 variational circuit, B=2^20 samples.
// prep: builds batch-independent tensor T_w[i0,i1,i2,i3] (81 float4).
// main: 2 samples/thread (one f32x2 pair), fully-factored contraction
//   z_w = sum_{i0} r0[i0] sum_{i1} r1[i1] sum_{i2} r2[i2] sum_{i3} r3[i3] T
// with r_q = (1, cos(x_q pi), sin(x_q pi)).
// Register-lean (target <=64 regs) so 4 blocks x 256 thr = 32 warps/SM resident:
// fma pipe (~9.3us floor) and smem pipe (~11us floor) overlap near their floors.

__device__ float4 g_T4[81];

#define PACKX2(d, lo, hi) \
    asm("mov.b64 %0, {%1, %2};" : "=l"(d) : "f"(lo), "f"(hi))
#define UNPACKX2(lo, hi, s) \
    asm("mov.b64 {%0, %1}, %2;" : "=f"(lo), "=f"(hi) : "l"(s))
#define FMAX2(d, a, b, c) \
    asm("fma.rn.f32x2 %0, %1, %2, %3;" : "=l"(d) : "l"(a), "l"(b), "l"(c))

// ---------------- prep ----------------
__global__ void __launch_bounds__(512) qc_prep_kernel(const float* __restrict__ w) {
    __shared__ float sUr[16][16], sUi[16][16];
    __shared__ float sA[4][16][16];
    int tid = threadIdx.x;

    if (tid < 16) {
        const int j = tid;
        float wv[16];
#pragma unroll
        for (int i = 0; i < 16; ++i) wv[i] = w[i];
        float re[16], im[16];
#pragma unroll
        for (int s = 0; s < 16; ++s) { re[s] = (s == j) ? 1.0f : 0.0f; im[s] = 0.0f; }
#pragma unroll
        for (int d = 0; d < 2; ++d) {
#pragma unroll
            for (int g = 0; g < 4; ++g) {
                const int cm = 8 >> g;
                const int tm = 8 >> ((g + 1) & 3);
                float tre[16], tim[16];
#pragma unroll
                for (int s = 0; s < 16; ++s) {
                    const int src = (s & cm) ? (s ^ tm) : s;
                    tre[s] = re[src]; tim[s] = im[src];
                }
#pragma unroll
                for (int s = 0; s < 16; ++s) { re[s] = tre[s]; im[s] = tim[s]; }
            }
#pragma unroll
            for (int qb = 0; qb < 4; ++qb) {
                const int m = 8 >> qb;
                float cy, sy; __sincosf(0.5f * wv[d * 8 + qb * 2 + 0], &sy, &cy);
#pragma unroll
                for (int s = 0; s < 16; ++s) {
                    if (s & m) continue;
                    const int s1 = s | m;
                    float r0 = re[s], i0 = im[s], r1 = re[s1], i1 = im[s1];
                    re[s]  = cy * r0 - sy * r1;  im[s]  = cy * i0 - sy * i1;
                    re[s1] = sy * r0 + cy * r1;  im[s1] = sy * i0 + cy * i1;
                }
                float cp, sp; __sincosf(0.5f * wv[d * 8 + qb * 2 + 1], &sp, &cp);
#pragma unroll
                for (int s = 0; s < 16; ++s) {
                    float r = re[s], i = im[s];
                    if (s & m) { re[s] = r * cp - i * sp;  im[s] = i * cp + r * sp; }
                    else       { re[s] = r * cp + i * sp;  im[s] = i * cp - r * sp; }
                }
            }
        }
#pragma unroll
        for (int s = 0; s < 16; ++s) { sUr[s][j] = re[s]; sUi[s][j] = im[s]; }
    }
    __syncthreads();

    for (int e = tid; e < 1024; e += 512) {
        int wq = e >> 8;
        int j  = (e >> 4) & 15;
        int jp = e & 15;
        int mask = 8 >> wq;
        float acc = 0.f;
#pragma unroll
        for (int s = 0; s < 16; ++s) {
            float v = sUr[s][j] * sUr[s][jp] + sUi[s][j] * sUi[s][jp];
            acc += (s & mask) ? -v : v;
        }
        sA[wq][j][jp] = acc;
    }
    __syncthreads();

    if (tid < 324) {
        int wq = tid / 81;
        int kl = tid - wq * 81;
        int k = kl / 9, l = kl % 9;
        int i0 = k / 3, i1 = k % 3, i2 = l / 3, i3 = l % 3;
        int x0 = (i0 == 2), x1 = (i1 == 2), x2 = (i2 == 2), x3 = (i3 == 2);
        int n0 = (i0 == 1), n1 = (i1 == 1), n2 = (i2 == 1), n3 = (i3 == 1);
        float acc = 0.f;
#pragma unroll
        for (int c = 0; c < 16; ++c) {
            int o0 = (c >> 3) & 1, o1 = (c >> 2) & 1, o2 = (c >> 1) & 1, o3 = c & 1;
            int j  = (o0 << 3) | (o1 << 2) | (o2 << 1) | o3;
            int jp = ((o0 ^ x0) << 3) | ((o1 ^ x1) << 2) | ((o2 ^ x2) << 1) | (o3 ^ x3);
            int neg = (n0 & o0) ^ (n1 & o1) ^ (n2 & o2) ^ (n3 & o3);
            float v = sA[wq][j][jp];
            acc += neg ? -v : v;
        }
        ((float*)g_T4)[kl * 4 + wq] = acc * (1.0f / 16.0f);
    }
}

// ---------------- main: 2 samples/thread, register-lean ----------------
__global__ void __launch_bounds__(256, 4) qc_main_kernel(
    const float4* __restrict__ x, float4* __restrict__ out, int h /* B/2 */) {
    __shared__ float4 Ts[81];
    int tid = threadIdx.x;
    if (tid < 81) Ts[tid] = g_T4[tid];
    __syncthreads();

    int t = blockIdx.x * 256 + tid;
    if (t >= h) return;

    const float PI_F = 3.14159265358979323846f;
    float4 xa = x[t];
    float4 xb = x[t + h];

    float Cs[2][4], Ss[2][4];  // [sample][qubit]
    __sincosf(xa.x * PI_F, &Ss[0][0], &Cs[0][0]);
    __sincosf(xa.y * PI_F, &Ss[0][1], &Cs[0][1]);
    __sincosf(xa.z * PI_F, &Ss[0][2], &Cs[0][2]);
    __sincosf(xa.w * PI_F, &Ss[0][3], &Cs[0][3]);
    __sincosf(xb.x * PI_F, &Ss[1][0], &Cs[1][0]);
    __sincosf(xb.y * PI_F, &Ss[1][1], &Cs[1][1]);
    __sincosf(xb.z * PI_F, &Ss[1][2], &Cs[1][2]);
    __sincosf(xb.w * PI_F, &Ss[1][3], &Cs[1][3]);

    unsigned long long C[4], S[4];
#pragma unroll
    for (int qb = 0; qb < 4; ++qb) {
        PACKX2(C[qb], Cs[0][qb], Cs[1][qb]);
        PACKX2(S[qb], Ss[0][qb], Ss[1][qb]);
    }

    unsigned long long z[4];

// one wire component: v = Ta + C3*Tb + S3*Tc, folded into u[w] per i2.
#define ONEW(w, aa, bb, cc)                          \
    {                                                \
        unsigned long long ta, tb, tc, v;            \
        PACKX2(ta, aa, aa);                          \
        PACKX2(tb, bb, bb);                          \
        PACKX2(tc, cc, cc);                          \
        FMAX2(v, C[3], tb, ta);                      \
        FMAX2(v, S[3], tc, v);                       \
        if (i2 == 0) u[w] = v;                       \
        else if (i2 == 1) FMAX2(u[w], C[2], v, u[w]);\
        else              FMAX2(u[w], S[2], v, u[w]);\
    }

#pragma unroll
    for (int i0 = 0; i0 < 3; ++i0) {
        unsigned long long tt[4];
#pragma unroll
        for (int i1 = 0; i1 < 3; ++i1) {
            const int base = (i0 * 3 + i1) * 9;
            unsigned long long u[4];
#pragma unroll
            for (int i2 = 0; i2 < 3; ++i2) {
                float4 Ta = Ts[base + i2 * 3 + 0];
                float4 Tb = Ts[base + i2 * 3 + 1];
                float4 Tc = Ts[base + i2 * 3 + 2];
                ONEW(0, Ta.x, Tb.x, Tc.x)
                ONEW(1, Ta.y, Tb.y, Tc.y)
                ONEW(2, Ta.z, Tb.z, Tc.z)
                ONEW(3, Ta.w, Tb.w, Tc.w)
            }
#pragma unroll
            for (int w = 0; w < 4; ++w) {
                if (i1 == 0) tt[w] = u[w];
                else if (i1 == 1) FMAX2(tt[w], C[1], u[w], tt[w]);
                else              FMAX2(tt[w], S[1], u[w], tt[w]);
            }
        }
#pragma unroll
        for (int w = 0; w < 4; ++w) {
            if (i0 == 0) z[w] = tt[w];
            else if (i0 == 1) FMAX2(z[w], C[0], tt[w], z[w]);
            else              FMAX2(z[w], S[0], tt[w], z[w]);
        }
    }
#undef ONEW

    float zA[4], zB[4];
#pragma unroll
    for (int w = 0; w < 4; ++w) UNPACKX2(zA[w], zB[w], z[w]);

    out[t]     = make_float4(zA[0], zA[1], zA[2], zA[3]);
    out[t + h] = make_float4(zB[0], zB[1], zB[2], zB[3]);
}

extern "C" void kernel_launch(void* const* d_in, const int* in_sizes, int n_in,
                              void* d_out, int out_size) {
    const float* x = (const float*)d_in[0];       // [B,4]
    const float* w = (const float*)d_in[1];       // [2,4,2]
    float* out = (float*)d_out;                   // [B,4]
    int B = in_sizes[0] / 4;
    int h = B / 2;

    qc_prep_kernel<<<1, 512>>>(w);
    int blocks = (h + 255) / 256;
    qc_main_kernel<<<blocks, 256>>>((const float4*)x, (float4*)out, h);
}